// round 7
// baseline (speedup 1.0000x reference)
#include <cuda_runtime.h>
#include <math.h>
#include <stdint.h>

#define BB  4
#define SS  256
#define VV  64
#define HH  128
#define NHH 8
#define DHH 16
#define NLL 3
#define LLP1 11
#define MM  (BB*SS)   // 1024
#define KAB 96        // padded causal K (64 A + 11 Bl + 21 zero)

// -------- device scratch (static; allocation-free) --------
__device__ float g_adj[VV*VV*LLP1];
__device__ float g_Z1[(size_t)VV*MM*HH];
__device__ float g_Z2[(size_t)VV*MM*HH];
__device__ float g_Qb[(size_t)VV*MM*HH];
__device__ float g_Kb[(size_t)VV*MM*HH];
__device__ float g_AB[(size_t)VV*KAB*MM];   // k-major: [v][k][m]
__device__ float g_Wc[KAB*HH];
__device__ float g_weff[VV*HH];
__device__ float g_beff[VV];
__device__ float g_Wvy[(size_t)VV*HH*NHH];  // [v][h][n]
__device__ float g_cy[VV*NHH];

__device__ __forceinline__ float* buf_sel(int s) {
    return (s == 0) ? g_Z1 : (s == 1) ? g_Z2 : (s == 2) ? g_Qb
         : (s == 3) ? g_Kb : g_AB;
}

__device__ __forceinline__ void cpasync16(uint32_t saddr, const void* g) {
    asm volatile("cp.async.cg.shared.global [%0], [%1], 16;\n" :: "r"(saddr), "l"(g));
}

// -------- sigmoid of adjacency logits --------
__global__ void sigmoid_adj_kernel(const float* __restrict__ logits) {
    int idx = blockIdx.x * blockDim.x + threadIdx.x;
    if (idx < VV*VV*LLP1) {
        float v = logits[idx];
        g_adj[idx] = 1.f / (1.f + expf(-v));
    }
}

// -------- build shared causal weight Wc[96][128] = [var_emb; temp_emb; 0] --------
__global__ void build_Wc_kernel(const float* __restrict__ var_emb,
                                const float* __restrict__ temp_emb) {
    int idx = blockIdx.x * 256 + threadIdx.x;
    if (idx >= KAB*HH) return;
    int r = idx >> 7, h = idx & 127;
    float val = 0.f;
    if (r < VV) val = var_emb[r*HH + h];
    else if (r < VV + LLP1) val = temp_emb[(r - VV)*HH + h];
    g_Wc[idx] = val;
}

// -------- fold O-proj into output head: weff[v]=Wo[v]@outW[v], beff[v]=bo.outW+outb --------
__global__ void build_weff_kernel(const float* __restrict__ Wo,
                                  const float* __restrict__ bo,
                                  const float* __restrict__ outW,
                                  const float* __restrict__ outb) {
    const int v = blockIdx.x;
    const int h = threadIdx.x;   // 128
    __shared__ float sw[HH];
    __shared__ float red[HH];
    sw[h] = outW[v*HH + h];
    __syncthreads();
    const float* wp = Wo + ((size_t)v*HH + h)*HH;
    float s = 0.f;
    #pragma unroll 8
    for (int k = 0; k < HH; k++) s = fmaf(wp[k], sw[k], s);
    g_weff[v*HH + h] = s;
    red[h] = bo[v*HH + h] * sw[h];
    __syncthreads();
    #pragma unroll
    for (int o = 64; o > 0; o >>= 1) {
        if (h < o) red[h] += red[h + o];
        __syncthreads();
    }
    if (h == 0) g_beff[v] = red[0] + outb[v];
}

// -------- fold V-proj through the head: Wvy[v,h,n] = sum_d Wv[v,h,n*16+d]*weff[v,n*16+d]
//          cy[v,n] = sum_d bv[v,n*16+d]*weff[v,n*16+d]   (runs after build_weff)
__global__ void build_Wvy_kernel(const float* __restrict__ Wv,
                                 const float* __restrict__ bv) {
    const int v = blockIdx.x;
    const int t = threadIdx.x;   // 256
    __shared__ float wsh[HH];
    if (t < HH) wsh[t] = g_weff[v*HH + t];
    __syncthreads();
    #pragma unroll
    for (int i = 0; i < 4; i++) {
        int e = t*4 + i;             // 0..1023
        int h = e >> 3, n = e & 7;
        const float* wp = Wv + ((size_t)v*HH + h)*HH + n*DHH;
        const float* gp = wsh + n*DHH;
        float s = 0.f;
        #pragma unroll
        for (int d = 0; d < DHH; d++) s = fmaf(wp[d], gp[d], s);
        g_Wvy[(size_t)v*HH*NHH + (size_t)h*NHH + n] = s;
    }
    if (t < NHH) {
        const float* bp = bv + (size_t)v*HH + t*DHH;
        const float* gp = wsh + t*DHH;
        float s = 0.f;
        #pragma unroll
        for (int d = 0; d < DHH; d++) s = fmaf(bp[d], gp[d], s);
        g_cy[v*NHH + t] = s;
    }
}

// -------- stage AB_T[i][k][m]: A (k<64), Bl (64<=k<75), zeros (75..95) --------
__global__ void __launch_bounds__(128) build_AB_kernel(const float* __restrict__ x) {
    const int i  = blockIdx.x;
    const int b  = blockIdx.y;
    const int t0 = blockIdx.z * 128;
    __shared__ float xsh[VV][140];
    __shared__ float adjs[VV][12];
    const int tid = threadIdx.x;     // 128

    for (int f = tid; f < 138*16; f += 128) {
        int j = f >> 4, s4 = f & 15;
        int t = t0 - 10 + j;
        float4 xv = make_float4(0.f, 0.f, 0.f, 0.f);
        if (t >= 0) xv = *(const float4*)(x + ((size_t)(b*SS + t))*VV + s4*4);
        xsh[s4*4+0][j] = xv.x;
        xsh[s4*4+1][j] = xv.y;
        xsh[s4*4+2][j] = xv.z;
        xsh[s4*4+3][j] = xv.w;
    }
    for (int f = tid; f < VV*LLP1; f += 128) {
        int s = f / LLP1, l = f - s*LLP1;
        adjs[s][l] = g_adj[((size_t)s*VV + i)*LLP1 + l];
    }
    __syncthreads();

    const int j0 = tid + 10;
    float bl[LLP1];
    #pragma unroll
    for (int l = 0; l < LLP1; l++) bl[l] = 0.f;

    float* ABi = g_AB + (size_t)i*KAB*MM + b*SS + t0;
    #pragma unroll 2
    for (int s = 0; s < VV; s++) {
        const float* xr = xsh[s];
        const float* ar = adjs[s];
        float a = 0.f;
        #pragma unroll
        for (int l = 0; l < LLP1; l++) {
            float p = xr[j0 - l] * ar[l];
            a += p;
            bl[l] += p;
        }
        ABi[(size_t)s*MM + tid] = a;
    }
    #pragma unroll
    for (int l = 0; l < LLP1; l++) ABi[(size_t)(VV + l)*MM + tid] = bl[l];
    #pragma unroll
    for (int r = VV + LLP1; r < KAB; r++) ABi[(size_t)r*MM + tid] = 0.f;
}

// -------- batched per-variable GEMM (64x128 tile, KT=32, double-buffered) --------
// MODE 0: bias + LayerNorm + exact GELU   MODE 1: bias   MODE 2: plain
template<int MODE, int KDIM, bool XT, bool SHW>
__global__ void __launch_bounds__(256, 2)
gemm2(int src, int dst,
      const float* __restrict__ Wall, const float* __restrict__ ball,
      const float* __restrict__ lng, const float* __restrict__ lnb, int li)
{
    constexpr int NK = KDIM / 32;
    __shared__ float As[2][32][64];   // 16 KB
    __shared__ float Bs[2][32][128];  // 32 KB  (total 48 KB exactly)
    const uint32_t As_u = (uint32_t)__cvta_generic_to_shared(&As[0][0][0]);
    const uint32_t Bs_u = (uint32_t)__cvta_generic_to_shared(&Bs[0][0][0]);

    const int v   = blockIdx.y;
    const int m0  = blockIdx.x * 64;
    const int tid = threadIdx.x;
    const int w = tid >> 5, lane = tid & 31;

    const float* Xb = buf_sel(src);
    const float* Xv = XT ? (Xb + (size_t)v*KDIM*MM)
                         : (Xb + ((size_t)v*MM + m0)*KDIM);
    const float* Wv = SHW ? g_Wc
                    : (MODE == 0 ? Wall + ((size_t)v*NLL + li)*HH*HH
                                 : Wall + (size_t)v*HH*HH);

    float acc[8][4];
    #pragma unroll
    for (int r = 0; r < 8; r++) { acc[r][0]=0.f; acc[r][1]=0.f; acc[r][2]=0.f; acc[r][3]=0.f; }

    const int am = tid >> 2, ak = tid & 3;
    const int xkr = tid >> 3, xms = tid & 7;
    float4 pa0, pa1;

    auto issueA = [&](int k0, int buf) {
        if (XT) {
            const float* g = Xv + (size_t)(k0 + xkr)*MM + m0 + xms*8;
            uint32_t d = As_u + (uint32_t)((buf*2048 + xkr*64 + xms*8) * 4);
            cpasync16(d, g);
            cpasync16(d + 16, g + 4);
        } else {
            const float* g = Xv + (size_t)am*KDIM + k0 + ak*8;
            pa0 = *(const float4*)g;
            pa1 = *(const float4*)(g + 4);
        }
    };
    auto storeA = [&](int buf) {
        if (!XT) {
            float* base = &As[buf][0][0] + am;
            base[(ak*8+0)*64] = pa0.x; base[(ak*8+1)*64] = pa0.y;
            base[(ak*8+2)*64] = pa0.z; base[(ak*8+3)*64] = pa0.w;
            base[(ak*8+4)*64] = pa1.x; base[(ak*8+5)*64] = pa1.y;
            base[(ak*8+6)*64] = pa1.z; base[(ak*8+7)*64] = pa1.w;
        }
    };
    auto issueB = [&](int k0, int buf) {
        #pragma unroll
        for (int i2 = 0; i2 < 4; i2++) {
            int s = tid + i2*256;
            int kr = s >> 5, c4 = (s & 31) << 2;
            uint32_t d = Bs_u + (uint32_t)((buf*4096 + kr*128 + c4) * 4);
            cpasync16(d, Wv + (size_t)(k0 + kr)*HH + c4);
        }
    };

    issueA(0, 0);
    issueB(0, 0);
    storeA(0);
    asm volatile("cp.async.commit_group;\n");
    asm volatile("cp.async.wait_group 0;\n" ::: "memory");
    __syncthreads();

    #pragma unroll 1
    for (int kt = 0; kt < NK; kt++) {
        const int cur = kt & 1, nxt = cur ^ 1;
        if (kt + 1 < NK) {
            issueA((kt + 1)*32, nxt);
            issueB((kt + 1)*32, nxt);
            asm volatile("cp.async.commit_group;\n");
        }
        const float* Ap = &As[cur][0][0] + w*8;
        const float* Bp = &Bs[cur][0][0] + (lane << 2);
        #pragma unroll 8
        for (int kk = 0; kk < 32; kk++) {
            float4 a0 = *(const float4*)(Ap + kk*64);
            float4 a1 = *(const float4*)(Ap + kk*64 + 4);
            float4 b  = *(const float4*)(Bp + kk*128);
            float ar[8] = {a0.x,a0.y,a0.z,a0.w,a1.x,a1.y,a1.z,a1.w};
            #pragma unroll
            for (int r = 0; r < 8; r++) {
                acc[r][0] = fmaf(ar[r], b.x, acc[r][0]);
                acc[r][1] = fmaf(ar[r], b.y, acc[r][1]);
                acc[r][2] = fmaf(ar[r], b.z, acc[r][2]);
                acc[r][3] = fmaf(ar[r], b.w, acc[r][3]);
            }
        }
        if (kt + 1 < NK) {
            storeA(nxt);
            asm volatile("cp.async.wait_group 0;\n" ::: "memory");
            __syncthreads();
        }
    }

    if (MODE < 2) {
        const float* bv = (MODE == 0) ? ball + ((size_t)v*NLL + li)*HH
                                      : ball + (size_t)v*HH;
        float4 bias = *(const float4*)(bv + lane*4);
        #pragma unroll
        for (int r = 0; r < 8; r++) {
            acc[r][0] += bias.x; acc[r][1] += bias.y;
            acc[r][2] += bias.z; acc[r][3] += bias.w;
        }
    }

    if (MODE == 0) {
        const float* gp = lng + ((size_t)v*NLL + li)*HH;
        const float* bp = lnb + ((size_t)v*NLL + li)*HH;
        float4 gv4 = *(const float4*)(gp + lane*4);
        float4 bv4 = *(const float4*)(bp + lane*4);
        float gg[4] = {gv4.x, gv4.y, gv4.z, gv4.w};
        float bt[4] = {bv4.x, bv4.y, bv4.z, bv4.w};
        #pragma unroll
        for (int r = 0; r < 8; r++) {
            float s1 = acc[r][0] + acc[r][1] + acc[r][2] + acc[r][3];
            float s2 = acc[r][0]*acc[r][0] + acc[r][1]*acc[r][1]
                     + acc[r][2]*acc[r][2] + acc[r][3]*acc[r][3];
            #pragma unroll
            for (int o = 16; o > 0; o >>= 1) {
                s1 += __shfl_xor_sync(0xffffffffu, s1, o);
                s2 += __shfl_xor_sync(0xffffffffu, s2, o);
            }
            float mu  = s1 * (1.f/128.f);
            float var = s2 * (1.f/128.f) - mu*mu;
            float inv = rsqrtf(var + 1e-5f);
            #pragma unroll
            for (int c = 0; c < 4; c++) {
                float xx = (acc[r][c] - mu) * inv * gg[c] + bt[c];
                acc[r][c] = 0.5f * xx * (1.f + erff(xx * 0.70710678118654752f));
            }
        }
    }

    float* Yv = buf_sel(dst) + ((size_t)v*MM + m0)*HH;
    #pragma unroll
    for (int r = 0; r < 8; r++) {
        float4 st = make_float4(acc[r][0], acc[r][1], acc[r][2], acc[r][3]);
        *(float4*)(Yv + (size_t)(w*8 + r)*HH + lane*4) = st;
    }
}

// -------- fused attention + V/O/head fold --------
// grid (V, B), 256 threads = one query each; loops over the 8 heads.
// out[m,v] = sum_n (sum_k softmax_k(q_n.k_n/4) * y[k,n]) + beff[v]
// y[k,n] = Z2[k,:].Wvy[v,:,n] + cy[v,n]
__global__ void __launch_bounds__(256) attn2_kernel(float* __restrict__ out) {
    const int v = blockIdx.x, b = blockIdx.y;
    __shared__ __align__(16) float Ks[SS][DHH];      // 16 KB
    __shared__ __align__(16) float ysh[NHH][SS];     // 8 KB
    __shared__ __align__(16) float wv_sh[HH][NHH];   // 4 KB

    const int t = threadIdx.x;
    const size_t base = ((size_t)v*MM + (size_t)b*SS)*HH;

    // stage Wvy[v] into smem
    {
        const float4* src = (const float4*)(g_Wvy + (size_t)v*HH*NHH);
        float4* dst = (float4*)&wv_sh[0][0];
        #pragma unroll
        for (int i = 0; i < HH*NHH/4/256; i++) dst[t + i*256] = src[t + i*256];
    }
    __syncthreads();

    // y for own key row t, all heads
    {
        const float* zr = g_Z2 + base + (size_t)t*HH;
        float ya[NHH];
        #pragma unroll
        for (int n = 0; n < NHH; n++) ya[n] = g_cy[v*NHH + n];
        #pragma unroll 4
        for (int h0 = 0; h0 < HH; h0 += 4) {
            float4 z = *(const float4*)(zr + h0);
            const float zz[4] = {z.x, z.y, z.z, z.w};
            #pragma unroll
            for (int hi = 0; hi < 4; hi++) {
                float4 w0 = *(const float4*)&wv_sh[h0 + hi][0];
                float4 w1 = *(const float4*)&wv_sh[h0 + hi][4];
                ya[0] = fmaf(zz[hi], w0.x, ya[0]);
                ya[1] = fmaf(zz[hi], w0.y, ya[1]);
                ya[2] = fmaf(zz[hi], w0.z, ya[2]);
                ya[3] = fmaf(zz[hi], w0.w, ya[3]);
                ya[4] = fmaf(zz[hi], w1.x, ya[4]);
                ya[5] = fmaf(zz[hi], w1.y, ya[5]);
                ya[6] = fmaf(zz[hi], w1.z, ya[6]);
                ya[7] = fmaf(zz[hi], w1.w, ya[7]);
            }
        }
        #pragma unroll
        for (int n = 0; n < NHH; n++) ysh[n][t] = ya[n];
    }

    float osum = 0.f;

    #pragma unroll 1
    for (int n = 0; n < NHH; n++) {
        __syncthreads();   // previous head's readers done before overwriting Ks
        {
            const float* Kp = g_Kb + base + (size_t)t*HH + n*DHH;
            *(float4*)&Ks[t][0]  = *(const float4*)(Kp);
            *(float4*)&Ks[t][4]  = *(const float4*)(Kp + 4);
            *(float4*)&Ks[t][8]  = *(const float4*)(Kp + 8);
            *(float4*)&Ks[t][12] = *(const float4*)(Kp + 12);
        }
        __syncthreads();

        const float* Qp = g_Qb + base + (size_t)t*HH + n*DHH;
        float4 q0 = *(const float4*)(Qp);
        float4 q1 = *(const float4*)(Qp + 4);
        float4 q2 = *(const float4*)(Qp + 8);
        float4 q3 = *(const float4*)(Qp + 12);
        const float sc = 0.25f;
        q0.x*=sc; q0.y*=sc; q0.z*=sc; q0.w*=sc;
        q1.x*=sc; q1.y*=sc; q1.z*=sc; q1.w*=sc;
        q2.x*=sc; q2.y*=sc; q2.z*=sc; q2.w*=sc;
        q3.x*=sc; q3.y*=sc; q3.z*=sc; q3.w*=sc;

        float mx = -3.0e38f, lsum = 0.f, acc = 0.f;
        const float* yrow = ysh[n];

        #pragma unroll 2
        for (int j = 0; j < SS; j += 2) {
            const float4* kr0 = (const float4*)Ks[j];
            const float4* kr1 = (const float4*)Ks[j+1];
            float4 ka0=kr0[0], ka1=kr0[1], ka2=kr0[2], ka3=kr0[3];
            float4 kb0=kr1[0], kb1=kr1[1], kb2=kr1[2], kb3=kr1[3];
            float sa = ((q0.x*ka0.x + q0.y*ka0.y) + (q0.z*ka0.z + q0.w*ka0.w))
                     + ((q1.x*ka1.x + q1.y*ka1.y) + (q1.z*ka1.z + q1.w*ka1.w))
                     + ((q2.x*ka2.x + q2.y*ka2.y) + (q2.z*ka2.z + q2.w*ka2.w))
                     + ((q3.x*ka3.x + q3.y*ka3.y) + (q3.z*ka3.z + q3.w*ka3.w));
            float sb = ((q0.x*kb0.x + q0.y*kb0.y) + (q0.z*kb0.z + q0.w*kb0.w))
                     + ((q1.x*kb1.x + q1.y*kb1.y) + (q1.z*kb1.z + q1.w*kb1.w))
                     + ((q2.x*kb2.x + q2.y*kb2.y) + (q2.z*kb2.z + q2.w*kb2.w))
                     + ((q3.x*kb3.x + q3.y*kb3.y) + (q3.z*kb3.z + q3.w*kb3.w));
            float mn = fmaxf(sa, sb);
            if (mn > mx) {
                float f = __expf(mx - mn);
                lsum *= f;
                acc  *= f;
                mx = mn;
            }
            float pa = __expf(sa - mx);
            float pb = __expf(sb - mx);
            float2 y2 = *(const float2*)&yrow[j];
            lsum += pa + pb;
            acc = fmaf(pa, y2.x, fmaf(pb, y2.y, acc));
        }
        osum += acc / lsum;
    }

    out[((size_t)b*SS + t)*VV + v] = osum + g_beff[v];
}

extern "C" void kernel_launch(void* const* d_in, const int* in_sizes, int n_in,
                              void* d_out, int out_size) {
    const float* x        = (const float*)d_in[0];
    const float* adjl     = (const float*)d_in[1];
    const float* var_emb  = (const float*)d_in[2];
    const float* temp_emb = (const float*)d_in[3];
    const float* mech_W   = (const float*)d_in[4];
    const float* mech_b   = (const float*)d_in[5];
    const float* ln_g     = (const float*)d_in[6];
    const float* ln_b     = (const float*)d_in[7];
    const float* Wq       = (const float*)d_in[8];
    const float* Wk       = (const float*)d_in[9];
    const float* Wv       = (const float*)d_in[10];
    const float* Wo       = (const float*)d_in[11];
    const float* bq       = (const float*)d_in[12];
    const float* bk       = (const float*)d_in[13];
    const float* bv       = (const float*)d_in[14];
    const float* bo       = (const float*)d_in[15];
    const float* out_W    = (const float*)d_in[16];
    const float* out_b    = (const float*)d_in[17];
    float* out = (float*)d_out;

    sigmoid_adj_kernel<<<(VV*VV*LLP1 + 255)/256, 256>>>(adjl);
    build_Wc_kernel<<<(KAB*HH + 255)/256, 256>>>(var_emb, temp_emb);
    build_weff_kernel<<<VV, 128>>>(Wo, bo, out_W, out_b);
    build_Wvy_kernel<<<VV, 256>>>(Wv, bv);
    build_AB_kernel<<<dim3(VV, BB, 2), 128>>>(x);

    // causal z = AB @ Wc  -> Z1
    gemm2<2,KAB,true,true><<<dim3(16, VV), 256>>>(4, 0, nullptr, nullptr, nullptr, nullptr, 0);

    // mech layers: Z1 -> Z2 -> Z1 -> Z2
    gemm2<0,128,false,false><<<dim3(16, VV), 256>>>(0, 1, mech_W, mech_b, ln_g, ln_b, 0);
    gemm2<0,128,false,false><<<dim3(16, VV), 256>>>(1, 0, mech_W, mech_b, ln_g, ln_b, 1);
    gemm2<0,128,false,false><<<dim3(16, VV), 256>>>(0, 1, mech_W, mech_b, ln_g, ln_b, 2);

    // Q/K projections from Z2 (V-projection folded into attention via Wvy)
    gemm2<1,128,false,false><<<dim3(16, VV), 256>>>(1, 2, Wq, bq, nullptr, nullptr, 0);
    gemm2<1,128,false,false><<<dim3(16, VV), 256>>>(1, 3, Wk, bk, nullptr, nullptr, 0);

    // fused attention + V/O/head fold -> writes out directly
    attn2_kernel<<<dim3(VV, BB), 256>>>(out);
}

// round 8
// speedup vs baseline: 1.7936x; 1.7936x over previous
#include <cuda_runtime.h>
#include <math.h>
#include <stdint.h>

#define BB  4
#define SS  256
#define VV  64
#define HH  128
#define NHH 8
#define DHH 16
#define NLL 3
#define LLP1 11
#define MM  (BB*SS)   // 1024
#define KAB 96        // padded causal K (64 A + 11 Bl + 21 zero)

// -------- device scratch (static; allocation-free) --------
__device__ float g_adj[VV*VV*LLP1];
__device__ float g_Z1[(size_t)VV*MM*HH];
__device__ float g_Z2[(size_t)VV*MM*HH];
__device__ float g_Qb[(size_t)VV*MM*HH];
__device__ float g_Kb[(size_t)VV*MM*HH];
__device__ float g_AB[(size_t)VV*KAB*MM];   // k-major: [v][k][m]
__device__ float g_Wc[KAB*HH];
__device__ float g_weff[VV*HH];
__device__ float g_beff[VV];
__device__ float g_Wvy[(size_t)VV*HH*NHH];  // [v][h][n]
__device__ float g_cy[VV*NHH];
__device__ float g_Y8[(size_t)NHH*VV*MM];   // [n][v][m]
__device__ float g_P[(size_t)NHH*VV*MM];    // per-head partial outputs [n][v][m]

__device__ __forceinline__ float* buf_sel(int s) {
    return (s == 0) ? g_Z1 : (s == 1) ? g_Z2 : (s == 2) ? g_Qb
         : (s == 3) ? g_Kb : g_AB;
}

__device__ __forceinline__ void cpasync16(uint32_t saddr, const void* g) {
    asm volatile("cp.async.cg.shared.global [%0], [%1], 16;\n" :: "r"(saddr), "l"(g));
}

// -------- sigmoid of adjacency logits --------
__global__ void sigmoid_adj_kernel(const float* __restrict__ logits) {
    int idx = blockIdx.x * blockDim.x + threadIdx.x;
    if (idx < VV*VV*LLP1) {
        float v = logits[idx];
        g_adj[idx] = 1.f / (1.f + expf(-v));
    }
}

// -------- build shared causal weight Wc[96][128] = [var_emb; temp_emb; 0] --------
__global__ void build_Wc_kernel(const float* __restrict__ var_emb,
                                const float* __restrict__ temp_emb) {
    int idx = blockIdx.x * 256 + threadIdx.x;
    if (idx >= KAB*HH) return;
    int r = idx >> 7, h = idx & 127;
    float val = 0.f;
    if (r < VV) val = var_emb[r*HH + h];
    else if (r < VV + LLP1) val = temp_emb[(r - VV)*HH + h];
    g_Wc[idx] = val;
}

// -------- fold O-proj into output head: weff[v]=Wo[v]@outW[v], beff[v]=bo.outW+outb --------
__global__ void build_weff_kernel(const float* __restrict__ Wo,
                                  const float* __restrict__ bo,
                                  const float* __restrict__ outW,
                                  const float* __restrict__ outb) {
    const int v = blockIdx.x;
    const int h = threadIdx.x;   // 128
    __shared__ float sw[HH];
    __shared__ float red[HH];
    sw[h] = outW[v*HH + h];
    __syncthreads();
    const float* wp = Wo + ((size_t)v*HH + h)*HH;
    float s = 0.f;
    #pragma unroll 8
    for (int k = 0; k < HH; k++) s = fmaf(wp[k], sw[k], s);
    g_weff[v*HH + h] = s;
    red[h] = bo[v*HH + h] * sw[h];
    __syncthreads();
    #pragma unroll
    for (int o = 64; o > 0; o >>= 1) {
        if (h < o) red[h] += red[h + o];
        __syncthreads();
    }
    if (h == 0) g_beff[v] = red[0] + outb[v];
}

// -------- fold V-proj through the head: Wvy[v,h,n] = sum_d Wv[v,h,n*16+d]*weff[v,n*16+d]
//          cy[v,n] = sum_d bv[v,n*16+d]*weff[v,n*16+d]   (runs after build_weff)
__global__ void build_Wvy_kernel(const float* __restrict__ Wv,
                                 const float* __restrict__ bv) {
    const int v = blockIdx.x;
    const int t = threadIdx.x;   // 256
    __shared__ float wsh[HH];
    if (t < HH) wsh[t] = g_weff[v*HH + t];
    __syncthreads();
    #pragma unroll
    for (int i = 0; i < 4; i++) {
        int e = i*256 + t;           // coalesced: consecutive t -> consecutive (h,n)
        int h = e >> 3, n = e & 7;
        const float* wp = Wv + ((size_t)v*HH + h)*HH + n*DHH;
        const float* gp = wsh + n*DHH;
        float s = 0.f;
        #pragma unroll
        for (int d = 0; d < DHH; d++) s = fmaf(wp[d], gp[d], s);
        g_Wvy[(size_t)v*HH*NHH + e] = s;
    }
    if (t < NHH) {
        const float* bp = bv + (size_t)v*HH + t*DHH;
        const float* gp = wsh + t*DHH;
        float s = 0.f;
        #pragma unroll
        for (int d = 0; d < DHH; d++) s = fmaf(bp[d], gp[d], s);
        g_cy[v*NHH + t] = s;
    }
}

// -------- stage AB_T[i][k][m]: A (k<64), Bl (64<=k<75), zeros (75..95) --------
__global__ void __launch_bounds__(128) build_AB_kernel(const float* __restrict__ x) {
    const int i  = blockIdx.x;
    const int b  = blockIdx.y;
    const int t0 = blockIdx.z * 128;
    __shared__ float xsh[VV][140];
    __shared__ float adjs[VV][12];
    const int tid = threadIdx.x;     // 128

    for (int f = tid; f < 138*16; f += 128) {
        int j = f >> 4, s4 = f & 15;
        int t = t0 - 10 + j;
        float4 xv = make_float4(0.f, 0.f, 0.f, 0.f);
        if (t >= 0) xv = *(const float4*)(x + ((size_t)(b*SS + t))*VV + s4*4);
        xsh[s4*4+0][j] = xv.x;
        xsh[s4*4+1][j] = xv.y;
        xsh[s4*4+2][j] = xv.z;
        xsh[s4*4+3][j] = xv.w;
    }
    for (int f = tid; f < VV*LLP1; f += 128) {
        int s = f / LLP1, l = f - s*LLP1;
        adjs[s][l] = g_adj[((size_t)s*VV + i)*LLP1 + l];
    }
    __syncthreads();

    const int j0 = tid + 10;
    float bl[LLP1];
    #pragma unroll
    for (int l = 0; l < LLP1; l++) bl[l] = 0.f;

    float* ABi = g_AB + (size_t)i*KAB*MM + b*SS + t0;
    #pragma unroll 2
    for (int s = 0; s < VV; s++) {
        const float* xr = xsh[s];
        const float* ar = adjs[s];
        float a = 0.f;
        #pragma unroll
        for (int l = 0; l < LLP1; l++) {
            float p = xr[j0 - l] * ar[l];
            a += p;
            bl[l] += p;
        }
        ABi[(size_t)s*MM + tid] = a;
    }
    #pragma unroll
    for (int l = 0; l < LLP1; l++) ABi[(size_t)(VV + l)*MM + tid] = bl[l];
    #pragma unroll
    for (int r = VV + LLP1; r < KAB; r++) ABi[(size_t)r*MM + tid] = 0.f;
}

// -------- batched per-variable GEMM (64x128 tile, KT=32, double-buffered) --------
// MODE 0: bias + LayerNorm + exact GELU   MODE 1: bias   MODE 2: plain
template<int MODE, int KDIM, bool XT, bool SHW>
__global__ void __launch_bounds__(256, 2)
gemm2(int src, int dst,
      const float* __restrict__ Wall, const float* __restrict__ ball,
      const float* __restrict__ lng, const float* __restrict__ lnb, int li)
{
    constexpr int NK = KDIM / 32;
    __shared__ float As[2][32][64];   // 16 KB
    __shared__ float Bs[2][32][128];  // 32 KB  (total 48 KB exactly)
    const uint32_t As_u = (uint32_t)__cvta_generic_to_shared(&As[0][0][0]);
    const uint32_t Bs_u = (uint32_t)__cvta_generic_to_shared(&Bs[0][0][0]);

    const int v   = blockIdx.y;
    const int m0  = blockIdx.x * 64;
    const int tid = threadIdx.x;
    const int w = tid >> 5, lane = tid & 31;

    const float* Xb = buf_sel(src);
    const float* Xv = XT ? (Xb + (size_t)v*KDIM*MM)
                         : (Xb + ((size_t)v*MM + m0)*KDIM);
    const float* Wv = SHW ? g_Wc
                    : (MODE == 0 ? Wall + ((size_t)v*NLL + li)*HH*HH
                                 : Wall + (size_t)v*HH*HH);

    float acc[8][4];
    #pragma unroll
    for (int r = 0; r < 8; r++) { acc[r][0]=0.f; acc[r][1]=0.f; acc[r][2]=0.f; acc[r][3]=0.f; }

    const int am = tid >> 2, ak = tid & 3;
    const int xkr = tid >> 3, xms = tid & 7;
    float4 pa0, pa1;

    auto issueA = [&](int k0, int buf) {
        if (XT) {
            const float* g = Xv + (size_t)(k0 + xkr)*MM + m0 + xms*8;
            uint32_t d = As_u + (uint32_t)((buf*2048 + xkr*64 + xms*8) * 4);
            cpasync16(d, g);
            cpasync16(d + 16, g + 4);
        } else {
            const float* g = Xv + (size_t)am*KDIM + k0 + ak*8;
            pa0 = *(const float4*)g;
            pa1 = *(const float4*)(g + 4);
        }
    };
    auto storeA = [&](int buf) {
        if (!XT) {
            float* base = &As[buf][0][0] + am;
            base[(ak*8+0)*64] = pa0.x; base[(ak*8+1)*64] = pa0.y;
            base[(ak*8+2)*64] = pa0.z; base[(ak*8+3)*64] = pa0.w;
            base[(ak*8+4)*64] = pa1.x; base[(ak*8+5)*64] = pa1.y;
            base[(ak*8+6)*64] = pa1.z; base[(ak*8+7)*64] = pa1.w;
        }
    };
    auto issueB = [&](int k0, int buf) {
        #pragma unroll
        for (int i2 = 0; i2 < 4; i2++) {
            int s = tid + i2*256;
            int kr = s >> 5, c4 = (s & 31) << 2;
            uint32_t d = Bs_u + (uint32_t)((buf*4096 + kr*128 + c4) * 4);
            cpasync16(d, Wv + (size_t)(k0 + kr)*HH + c4);
        }
    };

    issueA(0, 0);
    issueB(0, 0);
    storeA(0);
    asm volatile("cp.async.commit_group;\n");
    asm volatile("cp.async.wait_group 0;\n" ::: "memory");
    __syncthreads();

    #pragma unroll 1
    for (int kt = 0; kt < NK; kt++) {
        const int cur = kt & 1, nxt = cur ^ 1;
        if (kt + 1 < NK) {
            issueA((kt + 1)*32, nxt);
            issueB((kt + 1)*32, nxt);
            asm volatile("cp.async.commit_group;\n");
        }
        const float* Ap = &As[cur][0][0] + w*8;
        const float* Bp = &Bs[cur][0][0] + (lane << 2);
        #pragma unroll 8
        for (int kk = 0; kk < 32; kk++) {
            float4 a0 = *(const float4*)(Ap + kk*64);
            float4 a1 = *(const float4*)(Ap + kk*64 + 4);
            float4 b  = *(const float4*)(Bp + kk*128);
            float ar[8] = {a0.x,a0.y,a0.z,a0.w,a1.x,a1.y,a1.z,a1.w};
            #pragma unroll
            for (int r = 0; r < 8; r++) {
                acc[r][0] = fmaf(ar[r], b.x, acc[r][0]);
                acc[r][1] = fmaf(ar[r], b.y, acc[r][1]);
                acc[r][2] = fmaf(ar[r], b.z, acc[r][2]);
                acc[r][3] = fmaf(ar[r], b.w, acc[r][3]);
            }
        }
        if (kt + 1 < NK) {
            storeA(nxt);
            asm volatile("cp.async.wait_group 0;\n" ::: "memory");
            __syncthreads();
        }
    }

    if (MODE < 2) {
        const float* bv = (MODE == 0) ? ball + ((size_t)v*NLL + li)*HH
                                      : ball + (size_t)v*HH;
        float4 bias = *(const float4*)(bv + lane*4);
        #pragma unroll
        for (int r = 0; r < 8; r++) {
            acc[r][0] += bias.x; acc[r][1] += bias.y;
            acc[r][2] += bias.z; acc[r][3] += bias.w;
        }
    }

    if (MODE == 0) {
        const float* gp = lng + ((size_t)v*NLL + li)*HH;
        const float* bp = lnb + ((size_t)v*NLL + li)*HH;
        float4 gv4 = *(const float4*)(gp + lane*4);
        float4 bv4 = *(const float4*)(bp + lane*4);
        float gg[4] = {gv4.x, gv4.y, gv4.z, gv4.w};
        float bt[4] = {bv4.x, bv4.y, bv4.z, bv4.w};
        #pragma unroll
        for (int r = 0; r < 8; r++) {
            float s1 = acc[r][0] + acc[r][1] + acc[r][2] + acc[r][3];
            float s2 = acc[r][0]*acc[r][0] + acc[r][1]*acc[r][1]
                     + acc[r][2]*acc[r][2] + acc[r][3]*acc[r][3];
            #pragma unroll
            for (int o = 16; o > 0; o >>= 1) {
                s1 += __shfl_xor_sync(0xffffffffu, s1, o);
                s2 += __shfl_xor_sync(0xffffffffu, s2, o);
            }
            float mu  = s1 * (1.f/128.f);
            float var = s2 * (1.f/128.f) - mu*mu;
            float inv = rsqrtf(var + 1e-5f);
            #pragma unroll
            for (int c = 0; c < 4; c++) {
                float xx = (acc[r][c] - mu) * inv * gg[c] + bt[c];
                acc[r][c] = 0.5f * xx * (1.f + erff(xx * 0.70710678118654752f));
            }
        }
    }

    float* Yv = buf_sel(dst) + ((size_t)v*MM + m0)*HH;
    #pragma unroll
    for (int r = 0; r < 8; r++) {
        float4 st = make_float4(acc[r][0], acc[r][1], acc[r][2], acc[r][3]);
        *(float4*)(Yv + (size_t)(w*8 + r)*HH + lane*4) = st;
    }
}

// -------- y8: Y8[n][v][m] = Z2[v,m,:].Wvy[v,:,n] + cy[v,n] --------
__global__ void __launch_bounds__(256) y8_kernel() {
    const int v = blockIdx.x, b = blockIdx.y;
    __shared__ __align__(16) float wv_sh[HH][NHH];   // 4 KB
    const int t = threadIdx.x;
    {
        const float4* src = (const float4*)(g_Wvy + (size_t)v*HH*NHH);
        float4* dst = (float4*)&wv_sh[0][0];
        dst[t] = src[t];   // 256 * 16B = 4 KB
    }
    __syncthreads();

    const float* zr = g_Z2 + ((size_t)v*MM + (size_t)b*SS + t)*HH;
    float ya[NHH];
    #pragma unroll
    for (int n = 0; n < NHH; n++) ya[n] = g_cy[v*NHH + n];
    #pragma unroll 4
    for (int h0 = 0; h0 < HH; h0 += 4) {
        float4 z = *(const float4*)(zr + h0);
        const float zz[4] = {z.x, z.y, z.z, z.w};
        #pragma unroll
        for (int hi = 0; hi < 4; hi++) {
            float4 w0 = *(const float4*)&wv_sh[h0 + hi][0];
            float4 w1 = *(const float4*)&wv_sh[h0 + hi][4];
            ya[0] = fmaf(zz[hi], w0.x, ya[0]);
            ya[1] = fmaf(zz[hi], w0.y, ya[1]);
            ya[2] = fmaf(zz[hi], w0.z, ya[2]);
            ya[3] = fmaf(zz[hi], w0.w, ya[3]);
            ya[4] = fmaf(zz[hi], w1.x, ya[4]);
            ya[5] = fmaf(zz[hi], w1.y, ya[5]);
            ya[6] = fmaf(zz[hi], w1.z, ya[6]);
            ya[7] = fmaf(zz[hi], w1.w, ya[7]);
        }
    }
    const size_t mo = (size_t)v*MM + (size_t)b*SS + t;
    #pragma unroll
    for (int n = 0; n < NHH; n++) g_Y8[(size_t)n*VV*MM + mo] = ya[n];  // coalesced per n
}

// -------- attention: per-(head,v,b) block, one query/thread, scalar-y online softmax --------
__global__ void __launch_bounds__(256) attn3_kernel() {
    const int n = blockIdx.x, v = blockIdx.y, b = blockIdx.z;
    __shared__ __align__(16) float Ks[SS][DHH];   // 16 KB
    __shared__ float ys[SS];                      // 1 KB

    const int t = threadIdx.x;
    const size_t base = ((size_t)v*MM + (size_t)b*SS)*HH + n*DHH;
    const size_t mo = (size_t)v*MM + (size_t)b*SS + t;
    {
        const float* Kp = g_Kb + base + (size_t)t*HH;
        *(float4*)&Ks[t][0]  = *(const float4*)(Kp);
        *(float4*)&Ks[t][4]  = *(const float4*)(Kp + 4);
        *(float4*)&Ks[t][8]  = *(const float4*)(Kp + 8);
        *(float4*)&Ks[t][12] = *(const float4*)(Kp + 12);
        ys[t] = g_Y8[(size_t)n*VV*MM + mo];
    }

    const float* Qp = g_Qb + base + (size_t)t*HH;
    float4 q0 = *(const float4*)(Qp);
    float4 q1 = *(const float4*)(Qp + 4);
    float4 q2 = *(const float4*)(Qp + 8);
    float4 q3 = *(const float4*)(Qp + 12);
    const float sc = 0.25f;   // 1/sqrt(DH)
    q0.x*=sc; q0.y*=sc; q0.z*=sc; q0.w*=sc;
    q1.x*=sc; q1.y*=sc; q1.z*=sc; q1.w*=sc;
    q2.x*=sc; q2.y*=sc; q2.z*=sc; q2.w*=sc;
    q3.x*=sc; q3.y*=sc; q3.z*=sc; q3.w*=sc;
    __syncthreads();

    float mx = -3.0e38f, lsum = 0.f, acc = 0.f;

    #pragma unroll 2
    for (int j = 0; j < SS; j += 2) {
        const float4* kr0 = (const float4*)Ks[j];
        const float4* kr1 = (const float4*)Ks[j+1];
        float4 ka0=kr0[0], ka1=kr0[1], ka2=kr0[2], ka3=kr0[3];
        float4 kb0=kr1[0], kb1=kr1[1], kb2=kr1[2], kb3=kr1[3];
        float sa = ((q0.x*ka0.x + q0.y*ka0.y) + (q0.z*ka0.z + q0.w*ka0.w))
                 + ((q1.x*ka1.x + q1.y*ka1.y) + (q1.z*ka1.z + q1.w*ka1.w))
                 + ((q2.x*ka2.x + q2.y*ka2.y) + (q2.z*ka2.z + q2.w*ka2.w))
                 + ((q3.x*ka3.x + q3.y*ka3.y) + (q3.z*ka3.z + q3.w*ka3.w));
        float sb = ((q0.x*kb0.x + q0.y*kb0.y) + (q0.z*kb0.z + q0.w*kb0.w))
                 + ((q1.x*kb1.x + q1.y*kb1.y) + (q1.z*kb1.z + q1.w*kb1.w))
                 + ((q2.x*kb2.x + q2.y*kb2.y) + (q2.z*kb2.z + q2.w*kb2.w))
                 + ((q3.x*kb3.x + q3.y*kb3.y) + (q3.z*kb3.z + q3.w*kb3.w));
        float mn = fmaxf(sa, sb);
        if (mn > mx) {
            float f = __expf(mx - mn);
            lsum *= f;
            acc  *= f;
            mx = mn;
        }
        float pa = __expf(sa - mx);
        float pb = __expf(sb - mx);
        float2 y2 = *(const float2*)&ys[j];
        lsum += pa + pb;
        acc = fmaf(pa, y2.x, fmaf(pb, y2.y, acc));
    }

    g_P[(size_t)n*VV*MM + mo] = acc / lsum;
}

// -------- reduce heads + beff -> out[m][v] --------
__global__ void reduce_kernel(float* __restrict__ out) {
    const int e = blockIdx.x * 256 + threadIdx.x;   // e = v*MM + m
    if (e >= VV*MM) return;
    const int v = e >> 10;
    const int m = e & 1023;
    float s = g_beff[v];
    #pragma unroll
    for (int n = 0; n < NHH; n++) s += g_P[(size_t)n*VV*MM + e];
    out[(size_t)m*VV + v] = s;
}

extern "C" void kernel_launch(void* const* d_in, const int* in_sizes, int n_in,
                              void* d_out, int out_size) {
    const float* x        = (const float*)d_in[0];
    const float* adjl     = (const float*)d_in[1];
    const float* var_emb  = (const float*)d_in[2];
    const float* temp_emb = (const float*)d_in[3];
    const float* mech_W   = (const float*)d_in[4];
    const float* mech_b   = (const float*)d_in[5];
    const float* ln_g     = (const float*)d_in[6];
    const float* ln_b     = (const float*)d_in[7];
    const float* Wq       = (const float*)d_in[8];
    const float* Wk       = (const float*)d_in[9];
    const float* Wv       = (const float*)d_in[10];
    const float* Wo       = (const float*)d_in[11];
    const float* bq       = (const float*)d_in[12];
    const float* bk       = (const float*)d_in[13];
    const float* bv       = (const float*)d_in[14];
    const float* bo       = (const float*)d_in[15];
    const float* out_W    = (const float*)d_in[16];
    const float* out_b    = (const float*)d_in[17];
    float* out = (float*)d_out;

    sigmoid_adj_kernel<<<(VV*VV*LLP1 + 255)/256, 256>>>(adjl);
    build_Wc_kernel<<<(KAB*HH + 255)/256, 256>>>(var_emb, temp_emb);
    build_weff_kernel<<<VV, 128>>>(Wo, bo, out_W, out_b);
    build_Wvy_kernel<<<VV, 256>>>(Wv, bv);
    build_AB_kernel<<<dim3(VV, BB, 2), 128>>>(x);

    // causal z = AB @ Wc  -> Z1
    gemm2<2,KAB,true,true><<<dim3(16, VV), 256>>>(4, 0, nullptr, nullptr, nullptr, nullptr, 0);

    // mech layers: Z1 -> Z2 -> Z1 -> Z2
    gemm2<0,128,false,false><<<dim3(16, VV), 256>>>(0, 1, mech_W, mech_b, ln_g, ln_b, 0);
    gemm2<0,128,false,false><<<dim3(16, VV), 256>>>(1, 0, mech_W, mech_b, ln_g, ln_b, 1);
    gemm2<0,128,false,false><<<dim3(16, VV), 256>>>(0, 1, mech_W, mech_b, ln_g, ln_b, 2);

    // folded V path: Y8 = Z2 @ Wvy + cy
    y8_kernel<<<dim3(VV, BB), 256>>>();

    // Q/K projections from Z2
    gemm2<1,128,false,false><<<dim3(16, VV), 256>>>(1, 2, Wq, bq, nullptr, nullptr, 0);
    gemm2<1,128,false,false><<<dim3(16, VV), 256>>>(1, 3, Wk, bk, nullptr, nullptr, 0);

    // attention partials per head
    attn3_kernel<<<dim3(NHH, VV, BB), 256>>>();

    // sum heads + bias -> out
    reduce_kernel<<<(VV*MM + 255)/256, 256>>>(out);
}